// round 1
// baseline (speedup 1.0000x reference)
#include <cuda_runtime.h>

#define HW 4096
#define NB 8

// Scratch (device globals; no runtime allocation allowed)
__device__ float g_q[NB * HW * 32];            // [b][n][d]
__device__ float g_k[NB * HW * 32];            // [b][m][d]
__device__ float g_v[NB * HW * 64];            // [b][m][c]  (becomes w = v/Z in place)
__device__ float g_Z[NB * HW];                 // column sums of exp(am)
__device__ float g_out[NB * 64 * HW];          // [b][c][n] fp32 accumulator
__device__ float g_P[(size_t)NB * HW * HW];    // [b][m][n] = exp(am[n,m])  (512 MB)

// ---------------------------------------------------------------------------
// 0) zero the accumulators (graph replays require re-zeroing every call)
__global__ void init_kernel() {
    size_t i = (size_t)blockIdx.x * 256 + threadIdx.x;   // grid 8192*256 = 2,097,152
    g_out[i] = 0.0f;
    if (i < (size_t)NB * HW) g_Z[i] = 0.0f;
}

// ---------------------------------------------------------------------------
// 1) projections: q, k (with bias), v   — one thread per pixel
__global__ void proj_kernel(const float* __restrict__ x1, const float* __restrict__ x2,
                            const float* __restrict__ Wq, const float* __restrict__ bq,
                            const float* __restrict__ Wk, const float* __restrict__ bk,
                            const float* __restrict__ Wv) {
    __shared__ float wqs[32 * 64], wks[32 * 64], wvs[64 * 64], bqs[32], bks[32];
    int b = blockIdx.y;
    int n0 = blockIdx.x * 128;
    int t = threadIdx.x;

    for (int i = t; i < 32 * 64; i += 128) { wqs[i] = Wq[i]; wks[i] = Wk[i]; }
    for (int i = t; i < 64 * 64; i += 128) wvs[i] = Wv[i];
    if (t < 32) { bqs[t] = bq[t]; bks[t] = bk[t]; }
    __syncthreads();

    int n = n0 + t;
    float xv[64];
#pragma unroll
    for (int c = 0; c < 32; c++) {
        xv[c]      = x1[((size_t)b * 32 + c) * HW + n];
        xv[c + 32] = x2[((size_t)b * 32 + c) * HW + n];
    }

    size_t qbase = ((size_t)b * HW + n) * 32;
    for (int d = 0; d < 32; d++) {
        float aq = bqs[d], ak = bks[d];
#pragma unroll
        for (int c = 0; c < 64; c++) {
            aq = fmaf(wqs[d * 64 + c], xv[c], aq);
            ak = fmaf(wks[d * 64 + c], xv[c], ak);
        }
        g_q[qbase + d] = aq;
        g_k[qbase + d] = ak;
    }
    size_t vbase = ((size_t)b * HW + n) * 64;
    for (int o = 0; o < 64; o++) {
        float a = 0.0f;
#pragma unroll
        for (int c = 0; c < 64; c++) a = fmaf(wvs[o * 64 + c], xv[c], a);
        g_v[vbase + o] = a;
    }
}

// ---------------------------------------------------------------------------
// 2) attention: P[b][m][n] = exp(q[n]·k[m]),  Z[b][m] += column sums
// block tile 128n x 128m, K=32 fully resident; 256 threads, 8x8 per thread
__global__ void attn_kernel() {
    __shared__ float qs[32][128];   // [d][n]
    __shared__ float ks[32][128];   // [d][m]
    __shared__ float Zs[128];

    int b = blockIdx.z;
    int n0 = blockIdx.y * 128;
    int m0 = blockIdx.x * 128;
    int t = threadIdx.x;

    // load q / k tiles, transposing [n][d] -> [d][n]
    for (int i = t; i < 1024; i += 256) {
        int n = i / 8, dg = i % 8;
        float4 v = *(const float4*)&g_q[((size_t)b * HW + n0 + n) * 32 + dg * 4];
        qs[dg * 4 + 0][n] = v.x; qs[dg * 4 + 1][n] = v.y;
        qs[dg * 4 + 2][n] = v.z; qs[dg * 4 + 3][n] = v.w;
    }
    for (int i = t; i < 1024; i += 256) {
        int m = i / 8, dg = i % 8;
        float4 v = *(const float4*)&g_k[((size_t)b * HW + m0 + m) * 32 + dg * 4];
        ks[dg * 4 + 0][m] = v.x; ks[dg * 4 + 1][m] = v.y;
        ks[dg * 4 + 2][m] = v.z; ks[dg * 4 + 3][m] = v.w;
    }
    __syncthreads();

    int tn = t % 16, tm = t / 16;   // 16 x 16 thread grid
    float acc[8][8];                // [m][n]
#pragma unroll
    for (int i = 0; i < 8; i++)
#pragma unroll
        for (int j = 0; j < 8; j++) acc[i][j] = 0.0f;

    for (int d = 0; d < 32; d++) {
        float qv[8], pv[8];
        *(float4*)&qv[0] = *(float4*)&qs[d][tn * 8];
        *(float4*)&qv[4] = *(float4*)&qs[d][tn * 8 + 4];
        *(float4*)&pv[0] = *(float4*)&ks[d][tm * 8];
        *(float4*)&pv[4] = *(float4*)&ks[d][tm * 8 + 4];
#pragma unroll
        for (int i = 0; i < 8; i++)
#pragma unroll
            for (int j = 0; j < 8; j++) acc[i][j] = fmaf(pv[i], qv[j], acc[i][j]);
    }

    // exp + row (over n) partial sums + store P transposed
#pragma unroll
    for (int em = 0; em < 8; em++) {
        float rs = 0.0f;
#pragma unroll
        for (int en = 0; en < 8; en++) {
            float p = __expf(acc[em][en]);
            acc[em][en] = p;
            rs += p;
        }
        // reduce over the 16 tn-lanes sharing this m
        rs += __shfl_xor_sync(0xffffffffu, rs, 1);
        rs += __shfl_xor_sync(0xffffffffu, rs, 2);
        rs += __shfl_xor_sync(0xffffffffu, rs, 4);
        rs += __shfl_xor_sync(0xffffffffu, rs, 8);
        if (tn == 0) Zs[tm * 8 + em] = rs;   // unique writer per slot

        size_t rowoff = ((size_t)b * HW + m0 + tm * 8 + em) * HW + n0 + tn * 8;
        *(float4*)&g_P[rowoff]     = make_float4(acc[em][0], acc[em][1], acc[em][2], acc[em][3]);
        *(float4*)&g_P[rowoff + 4] = make_float4(acc[em][4], acc[em][5], acc[em][6], acc[em][7]);
    }
    __syncthreads();
    if (t < 128) atomicAdd(&g_Z[(size_t)b * HW + m0 + t], Zs[t]);
}

// ---------------------------------------------------------------------------
// 3) w = v / Z (in place)
__global__ void wdiv_kernel() {
    size_t i = (size_t)blockIdx.x * 256 + threadIdx.x;   // 8*4096*64 = 2,097,152
    size_t bm = i >> 6;
    g_v[i] = g_v[i] / g_Z[bm];
}

// ---------------------------------------------------------------------------
// 4) out[c,n] += sum_m w[c,m] * P[m,n]   — split-K=4, atomic accumulate
// block tile 64c x 128n, 128 threads, 8x8 per thread, KT=32
__global__ void out_gemm_kernel() {
    __shared__ float ws[32][64];    // [kk][c]
    __shared__ float ps[32][128];   // [kk][n]

    int b = blockIdx.z;
    int mc = blockIdx.y;            // 0..3
    int n0 = blockIdx.x * 128;
    int t = threadIdx.x;
    int c0 = (t / 16) * 8;          // 8 c-groups
    int n0t = (t % 16) * 8;         // 16 n-groups

    float acc[8][8];
#pragma unroll
    for (int i = 0; i < 8; i++)
#pragma unroll
        for (int j = 0; j < 8; j++) acc[i][j] = 0.0f;

    int mstart = mc * 1024;
    for (int m0 = mstart; m0 < mstart + 1024; m0 += 32) {
        __syncthreads();
        // w tile: 32 rows x 64 floats
        for (int i = t; i < 512; i += 128) {
            int kk = i / 16, cc = (i % 16) * 4;
            *(float4*)&ws[kk][cc] =
                *(const float4*)&g_v[((size_t)b * HW + m0 + kk) * 64 + cc];
        }
        // P tile: 32 rows x 128 floats
        for (int i = t; i < 1024; i += 128) {
            int kk = i / 32, nn = (i % 32) * 4;
            *(float4*)&ps[kk][nn] =
                *(const float4*)&g_P[((size_t)b * HW + m0 + kk) * HW + n0 + nn];
        }
        __syncthreads();

#pragma unroll
        for (int kk = 0; kk < 32; kk++) {
            float wv[8], pv[8];
            *(float4*)&wv[0] = *(float4*)&ws[kk][c0];
            *(float4*)&wv[4] = *(float4*)&ws[kk][c0 + 4];
            *(float4*)&pv[0] = *(float4*)&ps[kk][n0t];
            *(float4*)&pv[4] = *(float4*)&ps[kk][n0t + 4];
#pragma unroll
            for (int i = 0; i < 8; i++)
#pragma unroll
                for (int j = 0; j < 8; j++) acc[i][j] = fmaf(wv[i], pv[j], acc[i][j]);
        }
    }

#pragma unroll
    for (int i = 0; i < 8; i++)
#pragma unroll
        for (int j = 0; j < 8; j++)
            atomicAdd(&g_out[((size_t)b * 64 + c0 + i) * HW + n0 + n0t + j], acc[i][j]);
}

// ---------------------------------------------------------------------------
// 5) epilogue: y = Wsc @ (gamma*out + x)
__global__ void epilogue_kernel(const float* __restrict__ x1, const float* __restrict__ x2,
                                const float* __restrict__ Wsc, const float* __restrict__ gamma,
                                float* __restrict__ y) {
    __shared__ float wsc[32 * 64];
    int b = blockIdx.y;
    int n0 = blockIdx.x * 128;
    int t = threadIdx.x;
    for (int i = t; i < 32 * 64; i += 128) wsc[i] = Wsc[i];
    __syncthreads();

    float g = gamma[0];
    int n = n0 + t;
    float tv[64];
#pragma unroll
    for (int c = 0; c < 32; c++) {
        tv[c]      = fmaf(g, g_out[((size_t)b * 64 + c) * HW + n],      x1[((size_t)b * 32 + c) * HW + n]);
        tv[c + 32] = fmaf(g, g_out[((size_t)b * 64 + c + 32) * HW + n], x2[((size_t)b * 32 + c) * HW + n]);
    }
    for (int o = 0; o < 32; o++) {
        float a = 0.0f;
#pragma unroll
        for (int c = 0; c < 64; c++) a = fmaf(wsc[o * 64 + c], tv[c], a);
        y[((size_t)b * 32 + o) * HW + n] = a;   // coalesced: lanes are consecutive n
    }
}

// ---------------------------------------------------------------------------
extern "C" void kernel_launch(void* const* d_in, const int* in_sizes, int n_in,
                              void* d_out, int out_size) {
    const float* x1    = (const float*)d_in[0];
    const float* x2    = (const float*)d_in[1];
    const float* Wq    = (const float*)d_in[2];
    const float* bq    = (const float*)d_in[3];
    const float* Wk    = (const float*)d_in[4];
    const float* bk    = (const float*)d_in[5];
    const float* Wv    = (const float*)d_in[6];
    const float* Wsc   = (const float*)d_in[7];
    const float* gamma = (const float*)d_in[8];
    float* y = (float*)d_out;

    init_kernel<<<8192, 256>>>();
    proj_kernel<<<dim3(32, 8), 128>>>(x1, x2, Wq, bq, Wk, bk, Wv);
    attn_kernel<<<dim3(32, 32, 8), 256>>>();
    wdiv_kernel<<<8192, 256>>>();
    out_gemm_kernel<<<dim3(32, 4, 8), 128>>>();
    epilogue_kernel<<<dim3(32, 8), 128>>>(x1, x2, Wsc, gamma, y);
}

// round 2
// speedup vs baseline: 2.4781x; 2.4781x over previous
#include <cuda_runtime.h>
#include <cuda_bf16.h>
#include <cstdint>

#define HW 4096
#define NB 8

// Scratch (device globals; no runtime allocation allowed)
__device__ float g_q[NB * HW * 32];                   // [b][n][d]
__device__ float g_k[NB * HW * 32];                   // [b][m][d]
__device__ float g_v[NB * HW * 64];                   // [b][m][c]
__device__ float g_Z[NB * HW];                        // Z[m] = sum_n exp(am[n,m])
__device__ __nv_bfloat16 g_w[(size_t)NB * 64 * HW];   // [b][c][m] = v/Z in bf16
__device__ float g_outT[(size_t)NB * HW * 64];        // [b][n][c]

// ---------------------------------------------------------------------------
__device__ __forceinline__ uint32_t f2tf32(float x) {
    uint32_t r; asm("cvt.rna.tf32.f32 %0, %1;" : "=r"(r) : "f"(x)); return r;
}
__device__ __forceinline__ uint32_t pack_bf16(float lo, float hi) {
    __nv_bfloat162 h = __floats2bfloat162_rn(lo, hi);
    return *reinterpret_cast<uint32_t*>(&h);
}
__device__ __forceinline__ void mma_tf32(float d[4], const uint32_t a[4],
                                         const uint32_t b[2], const float c[4]) {
    asm volatile(
        "mma.sync.aligned.m16n8k8.row.col.f32.tf32.tf32.f32 "
        "{%0,%1,%2,%3},{%4,%5,%6,%7},{%8,%9},{%10,%11,%12,%13};"
        : "=f"(d[0]), "=f"(d[1]), "=f"(d[2]), "=f"(d[3])
        : "r"(a[0]), "r"(a[1]), "r"(a[2]), "r"(a[3]), "r"(b[0]), "r"(b[1]),
          "f"(c[0]), "f"(c[1]), "f"(c[2]), "f"(c[3]));
}
__device__ __forceinline__ void mma_bf16(float d[4], const uint32_t a[4],
                                         const uint32_t b[2], const float c[4]) {
    asm volatile(
        "mma.sync.aligned.m16n8k16.row.col.f32.bf16.bf16.f32 "
        "{%0,%1,%2,%3},{%4,%5,%6,%7},{%8,%9},{%10,%11,%12,%13};"
        : "=f"(d[0]), "=f"(d[1]), "=f"(d[2]), "=f"(d[3])
        : "r"(a[0]), "r"(a[1]), "r"(a[2]), "r"(a[3]), "r"(b[0]), "r"(b[1]),
          "f"(c[0]), "f"(c[1]), "f"(c[2]), "f"(c[3]));
}

// ---------------------------------------------------------------------------
// 1) projections: q, k (with bias), v  — one thread per pixel
__global__ void __launch_bounds__(128) proj_kernel(
        const float* __restrict__ x1, const float* __restrict__ x2,
        const float* __restrict__ Wq, const float* __restrict__ bq,
        const float* __restrict__ Wk, const float* __restrict__ bk,
        const float* __restrict__ Wv) {
    __shared__ float wqs[32 * 64], wks[32 * 64], wvs[64 * 64], bqs[32], bks[32];
    int b = blockIdx.y;
    int n0 = blockIdx.x * 128;
    int t = threadIdx.x;

    for (int i = t; i < 32 * 64; i += 128) { wqs[i] = Wq[i]; wks[i] = Wk[i]; }
    for (int i = t; i < 64 * 64; i += 128) wvs[i] = Wv[i];
    if (t < 32) { bqs[t] = bq[t]; bks[t] = bk[t]; }
    __syncthreads();

    int n = n0 + t;
    float xv[64];
#pragma unroll
    for (int c = 0; c < 32; c++) {
        xv[c]      = x1[((size_t)b * 32 + c) * HW + n];
        xv[c + 32] = x2[((size_t)b * 32 + c) * HW + n];
    }

    size_t qbase = ((size_t)b * HW + n) * 32;
    for (int d = 0; d < 32; d++) {
        float aq = bqs[d], ak = bks[d];
#pragma unroll
        for (int c = 0; c < 64; c++) {
            aq = fmaf(wqs[d * 64 + c], xv[c], aq);
            ak = fmaf(wks[d * 64 + c], xv[c], ak);
        }
        g_q[qbase + d] = aq;
        g_k[qbase + d] = ak;
    }
    size_t vbase = ((size_t)b * HW + n) * 64;
    for (int o = 0; o < 64; o++) {
        float a = 0.0f;
#pragma unroll
        for (int c = 0; c < 64; c++) a = fmaf(wvs[o * 64 + c], xv[c], a);
        g_v[vbase + o] = a;
    }
}

// ---------------------------------------------------------------------------
// 2) pass 1: Z[m] = sum_n exp(q[n]·k[m]) — tf32 mma, no atomics.
// Block: 128 m-rows (8 warps x 16), loops over all n in chunks of 64.
__global__ void __launch_bounds__(256) pass1_kernel() {
    __shared__ float sm[128 * 36];  // k-stage (128x36), then q chunks (64x36)
    uint32_t* smu = reinterpret_cast<uint32_t*>(sm);

    int b = blockIdx.y;
    int m0 = blockIdx.x * 128;
    int t = threadIdx.x, lane = t & 31, w = t >> 5;
    int gid = lane >> 2, tig = lane & 3;

    // stage k tile [128m][32d] as tf32
    for (int i = t; i < 128 * 8; i += 256) {
        int row = i >> 3, d4 = (i & 7) * 4;
        float4 v = *(const float4*)&g_k[((size_t)b * HW + m0 + row) * 32 + d4];
        uint32_t* p = &smu[row * 36 + d4];
        p[0] = f2tf32(v.x); p[1] = f2tf32(v.y); p[2] = f2tf32(v.z); p[3] = f2tf32(v.w);
    }
    __syncthreads();

    // resident A fragments (k rows for this warp): 4 k-steps x 4 regs
    uint32_t ak[4][4];
    int r0 = w * 16 + gid;
#pragma unroll
    for (int ks = 0; ks < 4; ks++) {
        ak[ks][0] = smu[r0 * 36 + tig + 8 * ks];
        ak[ks][1] = smu[(r0 + 8) * 36 + tig + 8 * ks];
        ak[ks][2] = smu[r0 * 36 + tig + 4 + 8 * ks];
        ak[ks][3] = smu[(r0 + 8) * 36 + tig + 4 + 8 * ks];
    }

    float z0 = 0.0f, z1 = 0.0f;
    for (int n0 = 0; n0 < HW; n0 += 64) {
        __syncthreads();
        for (int i = t; i < 64 * 8; i += 256) {
            int row = i >> 3, d4 = (i & 7) * 4;
            float4 v = *(const float4*)&g_q[((size_t)b * HW + n0 + row) * 32 + d4];
            uint32_t* p = &smu[row * 36 + d4];
            p[0] = f2tf32(v.x); p[1] = f2tf32(v.y); p[2] = f2tf32(v.z); p[3] = f2tf32(v.w);
        }
        __syncthreads();
#pragma unroll
        for (int j = 0; j < 8; j++) {
            float acc[4] = {0.f, 0.f, 0.f, 0.f};
            int bc = j * 8 + gid;
#pragma unroll
            for (int ks = 0; ks < 4; ks++) {
                uint32_t bb[2] = { smu[bc * 36 + tig + 8 * ks],
                                   smu[bc * 36 + tig + 4 + 8 * ks] };
                mma_tf32(acc, ak[ks], bb, acc);
            }
            z0 += __expf(acc[0]) + __expf(acc[1]);
            z1 += __expf(acc[2]) + __expf(acc[3]);
        }
    }
    // reduce over the 4 lanes (tig) sharing each m-row
    z0 += __shfl_xor_sync(0xffffffffu, z0, 1);
    z0 += __shfl_xor_sync(0xffffffffu, z0, 2);
    z1 += __shfl_xor_sync(0xffffffffu, z1, 1);
    z1 += __shfl_xor_sync(0xffffffffu, z1, 2);
    if (tig == 0) {
        g_Z[(size_t)b * HW + m0 + r0]     = z0;
        g_Z[(size_t)b * HW + m0 + r0 + 8] = z1;
    }
}

// ---------------------------------------------------------------------------
// 3) w[b][c][m] = bf16(v[b][m][c] / Z[b][m])  — transposed write, coalesced
__global__ void __launch_bounds__(256) wdiv_kernel() {
    size_t i = (size_t)blockIdx.x * 256 + threadIdx.x;  // 2,097,152 total
    int m = (int)(i & (HW - 1));
    int c = (int)((i >> 12) & 63);
    int b = (int)(i >> 18);
    float v = g_v[((size_t)b * HW + m) * 64 + c];
    g_w[i] = __float2bfloat16(v / g_Z[(size_t)b * HW + m]);
}

// ---------------------------------------------------------------------------
// 4) pass 2 (fused): outT[n][c] = sum_m exp(q[n]·k[m]) * w[c][m]
// Block: 128 n-rows (8 warps x 16), loops m in chunks of 64.
// QK tf32 mma -> exp -> bf16 A-frag reuse -> PV bf16 mma.
__global__ void __launch_bounds__(256) pass2_kernel() {
    __shared__ uint32_t sm[128 * 36];  // q-stage; then k [0,64*36) + w [64*36,128*36)
    uint32_t* kx = sm;
    uint32_t* ws = sm + 64 * 36;

    int b = blockIdx.y;
    int n0 = blockIdx.x * 128;
    int t = threadIdx.x, lane = t & 31, w = t >> 5;
    int gid = lane >> 2, tig = lane & 3;

    // stage q tile [128n][32d] as tf32
    for (int i = t; i < 128 * 8; i += 256) {
        int row = i >> 3, d4 = (i & 7) * 4;
        float4 v = *(const float4*)&g_q[((size_t)b * HW + n0 + row) * 32 + d4];
        uint32_t* p = &sm[row * 36 + d4];
        p[0] = f2tf32(v.x); p[1] = f2tf32(v.y); p[2] = f2tf32(v.z); p[3] = f2tf32(v.w);
    }
    __syncthreads();

    uint32_t aq[4][4];
    int r0 = w * 16 + gid;
#pragma unroll
    for (int ks = 0; ks < 4; ks++) {
        aq[ks][0] = sm[r0 * 36 + tig + 8 * ks];
        aq[ks][1] = sm[(r0 + 8) * 36 + tig + 8 * ks];
        aq[ks][2] = sm[r0 * 36 + tig + 4 + 8 * ks];
        aq[ks][3] = sm[(r0 + 8) * 36 + tig + 4 + 8 * ks];
    }

    float accO[8][4];
#pragma unroll
    for (int j = 0; j < 8; j++)
#pragma unroll
        for (int i = 0; i < 4; i++) accO[j][i] = 0.0f;

    const uint32_t* gw = reinterpret_cast<const uint32_t*>(g_w);

    for (int m0 = 0; m0 < HW; m0 += 64) {
        __syncthreads();
        // k chunk [64m][32d] -> tf32
        for (int i = t; i < 64 * 8; i += 256) {
            int row = i >> 3, d4 = (i & 7) * 4;
            float4 v = *(const float4*)&g_k[((size_t)b * HW + m0 + row) * 32 + d4];
            uint32_t* p = &kx[row * 36 + d4];
            p[0] = f2tf32(v.x); p[1] = f2tf32(v.y); p[2] = f2tf32(v.z); p[3] = f2tf32(v.w);
        }
        // w chunk [64c][64m] bf16 (as 32 u32 per row), coalesced along m
        for (int i = t; i < 64 * 32; i += 256) {
            int c = i >> 5, mq = i & 31;
            ws[c * 36 + mq] = gw[((size_t)b * 64 + c) * (HW / 2) + (m0 >> 1) + mq];
        }
        __syncthreads();

        // QK: S[16n x 64m] per warp
        float S[8][4];
#pragma unroll
        for (int j = 0; j < 8; j++) {
            S[j][0] = S[j][1] = S[j][2] = S[j][3] = 0.0f;
            int bc = j * 8 + gid;
#pragma unroll
            for (int ks = 0; ks < 4; ks++) {
                uint32_t bb[2] = { kx[bc * 36 + tig + 8 * ks],
                                   kx[bc * 36 + tig + 4 + 8 * ks] };
                mma_tf32(S[j], aq[ks], bb, S[j]);
            }
        }

        // exp + PV: A-frags built from S fragments (FA2 layout identity)
#pragma unroll
        for (int tt = 0; tt < 4; tt++) {
            uint32_t pa[4];
            pa[0] = pack_bf16(__expf(S[2 * tt][0]),     __expf(S[2 * tt][1]));
            pa[1] = pack_bf16(__expf(S[2 * tt][2]),     __expf(S[2 * tt][3]));
            pa[2] = pack_bf16(__expf(S[2 * tt + 1][0]), __expf(S[2 * tt + 1][1]));
            pa[3] = pack_bf16(__expf(S[2 * tt + 1][2]), __expf(S[2 * tt + 1][3]));
#pragma unroll
            for (int j2 = 0; j2 < 8; j2++) {
                uint32_t bb[2] = { ws[(j2 * 8 + gid) * 36 + 8 * tt + tig],
                                   ws[(j2 * 8 + gid) * 36 + 8 * tt + tig + 4] };
                mma_bf16(accO[j2], pa, bb, accO[j2]);
            }
        }
    }

    // store outT[b][n][c]
#pragma unroll
    for (int j2 = 0; j2 < 8; j2++) {
        int col = j2 * 8 + 2 * tig;
        size_t row_lo = ((size_t)b * HW + n0 + w * 16 + gid) * 64 + col;
        size_t row_hi = ((size_t)b * HW + n0 + w * 16 + gid + 8) * 64 + col;
        *(float2*)&g_outT[row_lo] = make_float2(accO[j2][0], accO[j2][1]);
        *(float2*)&g_outT[row_hi] = make_float2(accO[j2][2], accO[j2][3]);
    }
}

// ---------------------------------------------------------------------------
// 5) epilogue: y = Wsc @ (gamma*out + x), reading outT[b][n][c]
__global__ void __launch_bounds__(128) epilogue_kernel(
        const float* __restrict__ x1, const float* __restrict__ x2,
        const float* __restrict__ Wsc, const float* __restrict__ gamma,
        float* __restrict__ y) {
    __shared__ float wsc[32 * 64];
    int b = blockIdx.y;
    int n0 = blockIdx.x * 128;
    int t = threadIdx.x;
    for (int i = t; i < 32 * 64; i += 128) wsc[i] = Wsc[i];
    __syncthreads();

    float g = gamma[0];
    int n = n0 + t;
    float tv[64];
    const float4* orow = (const float4*)&g_outT[((size_t)b * HW + n) * 64];
#pragma unroll
    for (int q4 = 0; q4 < 16; q4++) {
        float4 o = orow[q4];
        int c = q4 * 4;
        float xa, xb, xc, xd;
        if (c < 32) {
            xa = x1[((size_t)b * 32 + c + 0) * HW + n];
            xb = x1[((size_t)b * 32 + c + 1) * HW + n];
            xc = x1[((size_t)b * 32 + c + 2) * HW + n];
            xd = x1[((size_t)b * 32 + c + 3) * HW + n];
        } else {
            xa = x2[((size_t)b * 32 + c - 32) * HW + n];
            xb = x2[((size_t)b * 32 + c - 31) * HW + n];
            xc = x2[((size_t)b * 32 + c - 30) * HW + n];
            xd = x2[((size_t)b * 32 + c - 29) * HW + n];
        }
        tv[c + 0] = fmaf(g, o.x, xa);
        tv[c + 1] = fmaf(g, o.y, xb);
        tv[c + 2] = fmaf(g, o.z, xc);
        tv[c + 3] = fmaf(g, o.w, xd);
    }
    for (int o = 0; o < 32; o++) {
        float a = 0.0f;
#pragma unroll
        for (int c = 0; c < 64; c++) a = fmaf(wsc[o * 64 + c], tv[c], a);
        y[((size_t)b * 32 + o) * HW + n] = a;
    }
}

// ---------------------------------------------------------------------------
extern "C" void kernel_launch(void* const* d_in, const int* in_sizes, int n_in,
                              void* d_out, int out_size) {
    (void)in_sizes; (void)n_in; (void)out_size;
    const float* x1    = (const float*)d_in[0];
    const float* x2    = (const float*)d_in[1];
    const float* Wq    = (const float*)d_in[2];
    const float* bq    = (const float*)d_in[3];
    const float* Wk    = (const float*)d_in[4];
    const float* bk    = (const float*)d_in[5];
    const float* Wv    = (const float*)d_in[6];
    const float* Wsc   = (const float*)d_in[7];
    const float* gamma = (const float*)d_in[8];
    float* y = (float*)d_out;

    proj_kernel<<<dim3(32, 8), 128>>>(x1, x2, Wq, bq, Wk, bk, Wv);
    pass1_kernel<<<dim3(32, 8), 256>>>();
    wdiv_kernel<<<8192, 256>>>();
    pass2_kernel<<<dim3(32, 8), 256>>>();
    epilogue_kernel<<<dim3(32, 8), 128>>>(x1, x2, Wsc, gamma, y);
}